// round 6
// baseline (speedup 1.0000x reference)
#include <cuda_runtime.h>
#include <cuda_bf16.h>

#define SDIM 128
#define CDIM 8
#define ROWS_PER_SLAB 16384          // 128*128 (d,h) rows per channel slab
#define WORDS_PER_SLAB 65536         // 128^3 / 32
#define NPACK_TASKS (1u << 19)       // total 32-bit words = 2^24/32
#define NTASK2 (1u << 22)            // pass-2 tasks: 4 voxels each
#define NBLK2 4096

__device__ double g_sum;
__device__ double g_cnt;
__device__ unsigned g_done;
__device__ uint4 g_pack[8 * ROWS_PER_SLAB];   // 2 MB bitmask: 1 uint4 = one 128-voxel row

// ---------- 128-bit row ops (bit w = word[w>>5] bit (w&31)) ----------
__device__ __forceinline__ uint4 band(uint4 a, uint4 b) {
    return make_uint4(a.x & b.x, a.y & b.y, a.z & b.z, a.w & b.w);
}
__device__ __forceinline__ uint4 shl1(uint4 a) {   // bit w -> w+1
    return make_uint4(a.x << 1, __funnelshift_l(a.x, a.y, 1),
                      __funnelshift_l(a.y, a.z, 1), __funnelshift_l(a.z, a.w, 1));
}
__device__ __forceinline__ uint4 shr1(uint4 a) {   // bit w -> w-1
    return make_uint4(__funnelshift_r(a.x, a.y, 1), __funnelshift_r(a.y, a.z, 1),
                      __funnelshift_r(a.z, a.w, 1), a.w >> 1);
}
__device__ __forceinline__ uint4 shl2(uint4 a) {
    return make_uint4(a.x << 2, __funnelshift_l(a.x, a.y, 2),
                      __funnelshift_l(a.y, a.z, 2), __funnelshift_l(a.z, a.w, 2));
}
__device__ __forceinline__ uint4 shr2(uint4 a) {
    return make_uint4(__funnelshift_r(a.x, a.y, 2), __funnelshift_r(a.y, a.z, 2),
                      __funnelshift_r(a.z, a.w, 2), a.w >> 2);
}
// r AND (r shifted +/-1 in w): rows at L1-distance 1 in (d,h)
__device__ __forceinline__ uint4 S1(uint4 a) { return band(a, band(shl1(a), shr1(a))); }

__device__ __forceinline__ unsigned pick(uint4 v, int s) {
    unsigned lo = (s & 1) ? v.y : v.x;
    unsigned hi = (s & 1) ? v.w : v.z;
    return (s & 2) ? hi : lo;
}

// ---------- Pass 1: bit-pack targets for active channels (+ reset accumulators) ----------
__global__ void __launch_bounds__(256)
pack_kernel(const float* __restrict__ targets,
            const unsigned int* __restrict__ mask)
{
    unsigned j = blockIdx.x * 256u + threadIdx.x;   // word index, < 2^19
    if (j == 0) { g_sum = 0.0; g_cnt = 0.0; g_done = 0u; }

    int slab = j >> 16;                              // 0..7
    int b = slab >> 2;
    int ch = ((slab & 3) << 1) + 1;
    if (mask[b * CDIM + ch] == 0u) return;           // inactive: never read later

    unsigned jin = j & (WORDS_PER_SLAB - 1);
    size_t base = ((size_t)(b * CDIM + ch) << 21) + ((size_t)jin << 5);

    unsigned bits = 0;
    #pragma unroll
    for (int k = 0; k < 8; ++k) {
        float4 v = __ldg((const float4*)(targets + base + k * 4));
        bits |= (v.x > 0.5f ? 1u : 0u) << (4 * k + 0);
        bits |= (v.y > 0.5f ? 1u : 0u) << (4 * k + 1);
        bits |= (v.z > 0.5f ? 1u : 0u) << (4 * k + 2);
        bits |= (v.w > 0.5f ? 1u : 0u) << (4 * k + 3);
    }
    ((unsigned*)g_pack)[j] = bits;
}

// ---------- Pass 2: BCE + erosion-from-bitmask + reduction + fused finalize ----------
__global__ void __launch_bounds__(256)
loss_kernel(const float* __restrict__ logits,
            const unsigned int* __restrict__ mask,
            const float* __restrict__ spatial,
            float* __restrict__ out)
{
    float vsum = 0.0f, csum = 0.0f;

    for (unsigned task = blockIdx.x * 256u + threadIdx.x; task < NTASK2;
         task += NBLK2 * 256u)
    {
        int slab = task >> 19;
        int b = slab >> 2;
        int ch = ((slab & 3) << 1) + 1;
        if (mask[b * CDIM + ch] == 0u) continue;

        int lane = task & 31;                         // which float4 within the row
        int rr = (task >> 5) & (ROWS_PER_SLAB - 1);   // d*128 + h
        int d = rr >> 7, h = rr & 127;
        int w0 = lane << 2;

        // independent vector loads: logits + spatial (issued back-to-back)
        size_t lix = ((size_t)(b * CDIM + ch) << 21) + ((size_t)rr << 7) + w0;
        float4 lg = __ldg((const float4*)(logits + lix));
        unsigned six = ((unsigned)b << 21) + ((unsigned)rr << 7) + w0;
        float4 sm = __ldg((const float4*)(spatial + six));

        const uint4* pk = g_pack + slab * ROWS_PER_SLAB;
        uint4 m00 = __ldg(pk + rr);
        unsigned tw = pick(m00, lane >> 3) >> (w0 & 31);   // 4 target bits in low nibble

        // double 6-conn erosion == erosion by L1-ball radius 2 (zero-padded)
        unsigned ebits = 0;
        if (d >= 2 && d <= 125 && h >= 2 && h <= 125) {    // warp-uniform branch
            uint4 e = band(m00, band(band(shl1(m00), shr1(m00)),
                                     band(shl2(m00), shr2(m00))));
            e = band(e, S1(__ldg(pk + rr + 128)));   // d+1
            e = band(e, S1(__ldg(pk + rr - 128)));   // d-1
            e = band(e, S1(__ldg(pk + rr + 1)));     // h+1
            e = band(e, S1(__ldg(pk + rr - 1)));     // h-1
            e = band(e, __ldg(pk + rr + 256));       // d+2
            e = band(e, __ldg(pk + rr - 256));       // d-2
            e = band(e, __ldg(pk + rr + 2));         // h+2
            e = band(e, __ldg(pk + rr - 2));         // h-2
            e = band(e, __ldg(pk + rr + 129));       // d+1,h+1
            e = band(e, __ldg(pk + rr + 127));       // d+1,h-1
            e = band(e, __ldg(pk + rr - 127));       // d-1,h+1
            e = band(e, __ldg(pk + rr - 129));       // d-1,h-1
            ebits = pick(e, lane >> 3) >> (w0 & 31);
        }

        #pragma unroll
        for (int k = 0; k < 4; ++k) {
            float l = (k == 0) ? lg.x : (k == 1) ? lg.y : (k == 2) ? lg.z : lg.w;
            float s = (k == 0) ? sm.x : (k == 1) ? sm.y : (k == 2) ? sm.z : sm.w;
            unsigned tb = (tw >> k) & 1u;
            unsigned bb = tb & (((ebits >> k) & 1u) ^ 1u);   // boundary bit
            float t = (float)tb;
            float u = __expf(-fabsf(l));
            float bce = fmaxf(l, 0.0f) - l * t + __logf(1.0f + u);
            float wgt = 1.0f + 4.0f * (float)bb;
            vsum += bce * wgt * s;
            csum += s;
        }
    }

    // warp reduce
    #pragma unroll
    for (int off = 16; off > 0; off >>= 1) {
        vsum += __shfl_down_sync(0xFFFFFFFFu, vsum, off);
        csum += __shfl_down_sync(0xFFFFFFFFu, csum, off);
    }
    __shared__ float s_v[8], s_c[8];
    int lane = threadIdx.x & 31, wid = threadIdx.x >> 5;
    if (lane == 0) { s_v[wid] = vsum; s_c[wid] = csum; }
    __syncthreads();
    if (wid == 0) {
        vsum = (lane < 8) ? s_v[lane] : 0.0f;
        csum = (lane < 8) ? s_c[lane] : 0.0f;
        #pragma unroll
        for (int off = 4; off > 0; off >>= 1) {
            vsum += __shfl_down_sync(0xFFFFFFFFu, vsum, off);
            csum += __shfl_down_sync(0xFFFFFFFFu, csum, off);
        }
        if (lane == 0) {
            if (vsum != 0.0f) atomicAdd(&g_sum, (double)vsum);
            if (csum != 0.0f) atomicAdd(&g_cnt, (double)csum);
            __threadfence();
            unsigned ticket = atomicAdd(&g_done, 1u);
            if (ticket == NBLK2 - 1u) {              // last block finalizes
                double n = g_cnt;
                double s = g_sum;
                out[0] = (n > 0.0) ? (float)(s / (n > 1.0 ? n : 1.0)) : 0.0f;
            }
        }
    }
}

extern "C" void kernel_launch(void* const* d_in, const int* in_sizes, int n_in,
                              void* d_out, int out_size) {
    const float*        logits  = (const float*)d_in[0];
    const float*        targets = (const float*)d_in[1];
    const unsigned int* mask    = (const unsigned int*)d_in[2];
    const float*        spatial = (const float*)d_in[3];
    float*              out     = (float*)d_out;

    pack_kernel<<<NPACK_TASKS / 256, 256>>>(targets, mask);
    loss_kernel<<<NBLK2, 256>>>(logits, mask, spatial, out);
}

// round 7
// speedup vs baseline: 1.1644x; 1.1644x over previous
#include <cuda_runtime.h>
#include <cuda_bf16.h>

#define SDIM 128
#define CDIM 8
#define ROWS_PER_SLAB 16384          // 128*128 (d,h) rows per channel slab
#define WORDS_PER_SLAB 65536         // 128^3 / 32
#define NPACK_TASKS (1u << 19)       // total 32-bit words = 2^24/32
#define NTASK2 (1u << 22)            // pass-2 tasks: 4 voxels each
#define NBLK2 4096

__device__ double g_sum;
__device__ double g_cnt;
__device__ unsigned g_done;
__device__ uint4 g_pack[8 * ROWS_PER_SLAB];   // 2 MB bitmask: 1 uint4 = one 128-voxel row

// ---------- 128-bit row ops (bit w = word[w>>5] bit (w&31)) ----------
__device__ __forceinline__ uint4 band(uint4 a, uint4 b) {
    return make_uint4(a.x & b.x, a.y & b.y, a.z & b.z, a.w & b.w);
}
__device__ __forceinline__ uint4 shl1(uint4 a) {   // bit w -> w+1
    return make_uint4(a.x << 1, __funnelshift_l(a.x, a.y, 1),
                      __funnelshift_l(a.y, a.z, 1), __funnelshift_l(a.z, a.w, 1));
}
__device__ __forceinline__ uint4 shr1(uint4 a) {   // bit w -> w-1
    return make_uint4(__funnelshift_r(a.x, a.y, 1), __funnelshift_r(a.y, a.z, 1),
                      __funnelshift_r(a.z, a.w, 1), a.w >> 1);
}
__device__ __forceinline__ uint4 shl2(uint4 a) {
    return make_uint4(a.x << 2, __funnelshift_l(a.x, a.y, 2),
                      __funnelshift_l(a.y, a.z, 2), __funnelshift_l(a.z, a.w, 2));
}
__device__ __forceinline__ uint4 shr2(uint4 a) {
    return make_uint4(__funnelshift_r(a.x, a.y, 2), __funnelshift_r(a.y, a.z, 2),
                      __funnelshift_r(a.z, a.w, 2), a.w >> 2);
}
__device__ __forceinline__ unsigned pick(uint4 v, int s) {
    unsigned lo = (s & 1) ? v.y : v.x;
    unsigned hi = (s & 1) ? v.w : v.z;
    return (s & 2) ? hi : lo;
}

// ---------- Pass 1: bit-pack targets for active channels (+ reset accumulators) ----------
__global__ void __launch_bounds__(256)
pack_kernel(const float* __restrict__ targets,
            const unsigned int* __restrict__ mask)
{
    unsigned j = blockIdx.x * 256u + threadIdx.x;   // word index, < 2^19
    if (j == 0) { g_sum = 0.0; g_cnt = 0.0; g_done = 0u; }

    int slab = j >> 16;                              // 0..7
    int b = slab >> 2;
    int ch = ((slab & 3) << 1) + 1;
    if (mask[b * CDIM + ch] == 0u) return;           // inactive: never read later

    unsigned jin = j & (WORDS_PER_SLAB - 1);
    size_t base = ((size_t)(b * CDIM + ch) << 21) + ((size_t)jin << 5);

    unsigned bits = 0;
    #pragma unroll
    for (int k = 0; k < 8; ++k) {
        float4 v = __ldg((const float4*)(targets + base + k * 4));
        bits |= (v.x > 0.5f ? 1u : 0u) << (4 * k + 0);
        bits |= (v.y > 0.5f ? 1u : 0u) << (4 * k + 1);
        bits |= (v.z > 0.5f ? 1u : 0u) << (4 * k + 2);
        bits |= (v.w > 0.5f ? 1u : 0u) << (4 * k + 3);
    }
    ((unsigned*)g_pack)[j] = bits;
}

// ---------- Pass 2: BCE + erosion-from-bitmask + reduction + fused finalize ----------
__global__ void __launch_bounds__(256)
loss_kernel(const float* __restrict__ logits,
            const unsigned int* __restrict__ mask,
            const float* __restrict__ spatial,
            float* __restrict__ out)
{
    // hoist channel mask into a per-thread 8-bit bitmap (L1-resident scalar loads, once)
    unsigned actmap = 0;
    #pragma unroll
    for (int s = 0; s < 8; ++s) {
        int b = s >> 2, ch = ((s & 3) << 1) + 1;
        actmap |= (mask[b * CDIM + ch] != 0u ? 1u : 0u) << s;
    }

    float vsum = 0.0f, csum = 0.0f;

    for (unsigned task = blockIdx.x * 256u + threadIdx.x; task < NTASK2;
         task += NBLK2 * 256u)
    {
        int slab = task >> 19;
        if (!((actmap >> slab) & 1u)) continue;
        int b = slab >> 2;
        int ch = ((slab & 3) << 1) + 1;

        int lane = task & 31;                         // which float4 within the row
        int rr = (task >> 5) & (ROWS_PER_SLAB - 1);   // d*128 + h
        int d = rr >> 7, h = rr & 127;
        int w0 = lane << 2;

        // independent vector loads: logits + spatial (issued back-to-back)
        size_t lix = ((size_t)(b * CDIM + ch) << 21) + ((size_t)rr << 7) + w0;
        float4 lg = __ldg((const float4*)(logits + lix));
        unsigned six = ((unsigned)b << 21) + ((unsigned)rr << 7) + w0;
        float4 sm = __ldg((const float4*)(spatial + six));

        const uint4* pk = g_pack + slab * ROWS_PER_SLAB;
        uint4 m00 = __ldg(pk + rr);
        unsigned tw = pick(m00, lane >> 3) >> (w0 & 31);   // 4 target bits in low nibble

        // double 6-conn erosion == erosion by L1-ball radius 2 (zero-padded).
        // e = m & q4 & shl1(m&q4) & shr1(m&q4) & shl2(m) & shr2(m) & R8
        //   q4 = AND of (d±1, h±1) rows (shift distributes over AND)
        //   R8 = AND of 8 plain rows (d±2, h±2, d±1&h±1 diagonals)
        unsigned ebits = 0;
        if (d >= 2 && d <= 125 && h >= 2 && h <= 125) {    // warp-uniform branch
            // cheap plain-row AND first; almost always annihilates everything
            uint4 R = band(m00, band(__ldg(pk + rr + 256), __ldg(pk + rr - 256)));
            R = band(R, band(__ldg(pk + rr + 2),   __ldg(pk + rr - 2)));
            R = band(R, band(__ldg(pk + rr + 129), __ldg(pk + rr + 127)));
            R = band(R, band(__ldg(pk + rr - 127), __ldg(pk + rr - 129)));
            if (R.x | R.y | R.z | R.w) {                   // warp-uniform, rarely taken
                uint4 q = band(band(__ldg(pk + rr + 128), __ldg(pk + rr - 128)),
                               band(__ldg(pk + rr + 1),   __ldg(pk + rr - 1)));
                uint4 u = band(m00, q);
                uint4 e = band(band(R, u), band(shl1(u), shr1(u)));
                e = band(e, band(shl2(m00), shr2(m00)));
                ebits = pick(e, lane >> 3) >> (w0 & 31);
            }
        }

        #pragma unroll
        for (int k = 0; k < 4; ++k) {
            float l = (k == 0) ? lg.x : (k == 1) ? lg.y : (k == 2) ? lg.z : lg.w;
            float s = (k == 0) ? sm.x : (k == 1) ? sm.y : (k == 2) ? sm.z : sm.w;
            unsigned tb = (tw >> k) & 1u;
            unsigned bb = tb & (((ebits >> k) & 1u) ^ 1u);   // boundary bit
            float t = (float)tb;
            float u = __expf(-fabsf(l));
            float bce = fmaxf(l, 0.0f) - l * t + __logf(1.0f + u);
            float wgt = 1.0f + 4.0f * (float)bb;
            vsum += bce * wgt * s;
            csum += s;
        }
    }

    // warp reduce
    #pragma unroll
    for (int off = 16; off > 0; off >>= 1) {
        vsum += __shfl_down_sync(0xFFFFFFFFu, vsum, off);
        csum += __shfl_down_sync(0xFFFFFFFFu, csum, off);
    }
    __shared__ float s_v[8], s_c[8];
    int lane = threadIdx.x & 31, wid = threadIdx.x >> 5;
    if (lane == 0) { s_v[wid] = vsum; s_c[wid] = csum; }
    __syncthreads();
    if (wid == 0) {
        vsum = (lane < 8) ? s_v[lane] : 0.0f;
        csum = (lane < 8) ? s_c[lane] : 0.0f;
        #pragma unroll
        for (int off = 4; off > 0; off >>= 1) {
            vsum += __shfl_down_sync(0xFFFFFFFFu, vsum, off);
            csum += __shfl_down_sync(0xFFFFFFFFu, csum, off);
        }
        if (lane == 0) {
            if (vsum != 0.0f) atomicAdd(&g_sum, (double)vsum);
            if (csum != 0.0f) atomicAdd(&g_cnt, (double)csum);
            __threadfence();
            unsigned ticket = atomicAdd(&g_done, 1u);
            if (ticket == NBLK2 - 1u) {              // last block finalizes
                double n = g_cnt;
                double s = g_sum;
                out[0] = (n > 0.0) ? (float)(s / (n > 1.0 ? n : 1.0)) : 0.0f;
            }
        }
    }
}

extern "C" void kernel_launch(void* const* d_in, const int* in_sizes, int n_in,
                              void* d_out, int out_size) {
    const float*        logits  = (const float*)d_in[0];
    const float*        targets = (const float*)d_in[1];
    const unsigned int* mask    = (const unsigned int*)d_in[2];
    const float*        spatial = (const float*)d_in[3];
    float*              out     = (float*)d_out;

    pack_kernel<<<NPACK_TASKS / 256, 256>>>(targets, mask);
    loss_kernel<<<NBLK2, 256>>>(logits, mask, spatial, out);
}